// round 15
// baseline (speedup 1.0000x reference)
#include <cuda_runtime.h>
#include <math.h>

#define B 16
#define T (1 << 20)
#define NTH 256
#define CHUNK 2048                // offset granule (fp64)
#define NCH (T / CHUNK)           // 512 chunks per row
#define NSUB (T / 256)            // 4096 256-elem pieces per row
#define CPB 8                     // chunks per pass-1 block
#define CHUNK1 (CHUNK * CPB)      // 16384 elems per pass-1 block
#define BPR (NCH / CPB)           // 64 pass-1 blocks per row
#define STEP (1.0f / 48000.0f)
#define RISE_RATIO 0.66f
#define EPSV 1e-6f
#define PI_F 3.14159265358979f
#define FULL 0xFFFFFFFFu

// scratch (no device-side allocation allowed)
__device__ float  g_partials[B * NCH];   // per-2048-elem sum of f0*STEP
__device__ double g_offsets[B * NCH];    // ps[b] + exclusive prefix across chunks
__device__ float  g_subexcl[B * NSUB];   // within-chunk exclusive prefix, 256-gran (x STEP)
__device__ int    g_count[B];            // per-row completion counters (self-resetting)

struct F8 { float v[8]; };

__device__ __forceinline__ F8 ld8(const float* p) {   // default cache policy (k_wav only)
    unsigned r0,r1,r2,r3,r4,r5,r6,r7;
    asm("ld.global.v8.b32 {%0,%1,%2,%3,%4,%5,%6,%7}, [%8];"
        : "=r"(r0),"=r"(r1),"=r"(r2),"=r"(r3),"=r"(r4),"=r"(r5),"=r"(r6),"=r"(r7)
        : "l"(p));
    F8 f;
    f.v[0]=__uint_as_float(r0); f.v[1]=__uint_as_float(r1);
    f.v[2]=__uint_as_float(r2); f.v[3]=__uint_as_float(r3);
    f.v[4]=__uint_as_float(r4); f.v[5]=__uint_as_float(r5);
    f.v[6]=__uint_as_float(r6); f.v[7]=__uint_as_float(r7);
    return f;
}
__device__ __forceinline__ F8 ld8_ef(const float* p) {  // L2 evict-first (streaming)
    unsigned r0,r1,r2,r3,r4,r5,r6,r7;
    asm("ld.global.L2::evict_first.v8.b32 {%0,%1,%2,%3,%4,%5,%6,%7}, [%8];"
        : "=r"(r0),"=r"(r1),"=r"(r2),"=r"(r3),"=r"(r4),"=r"(r5),"=r"(r6),"=r"(r7)
        : "l"(p));
    F8 f;
    f.v[0]=__uint_as_float(r0); f.v[1]=__uint_as_float(r1);
    f.v[2]=__uint_as_float(r2); f.v[3]=__uint_as_float(r3);
    f.v[4]=__uint_as_float(r4); f.v[5]=__uint_as_float(r5);
    f.v[6]=__uint_as_float(r6); f.v[7]=__uint_as_float(r7);
    return f;
}
__device__ __forceinline__ void st8_ef(float* p, const float* w) {
    asm volatile("st.global.L2::evict_first.v8.b32 [%0], {%1,%2,%3,%4,%5,%6,%7,%8};"
        :: "l"(p),
           "r"(__float_as_uint(w[0])), "r"(__float_as_uint(w[1])),
           "r"(__float_as_uint(w[2])), "r"(__float_as_uint(w[3])),
           "r"(__float_as_uint(w[4])), "r"(__float_as_uint(w[5])),
           "r"(__float_as_uint(w[6])), "r"(__float_as_uint(w[7])) : "memory");
}

// sum the 8 packed f32 values inside a double4 (register aliasing, no converts)
__device__ __forceinline__ float sum8_of_d4(const double4& d) {
    const float e0 = __int_as_float(__double2loint(d.x));
    const float e1 = __int_as_float(__double2hiint(d.x));
    const float e2 = __int_as_float(__double2loint(d.y));
    const float e3 = __int_as_float(__double2hiint(d.y));
    const float e4 = __int_as_float(__double2loint(d.z));
    const float e5 = __int_as_float(__double2hiint(d.z));
    const float e6 = __int_as_float(__double2loint(d.w));
    const float e7 = __int_as_float(__double2hiint(d.w));
    return ((e0 + e1) + (e2 + e3)) + ((e4 + e5) + (e6 + e7));
}

// ------- Pass 1: slot layout warp<->256-piece; plain double4 loads; 8 trees --
// Slot s: block reads chunk s (8KB contiguous); warp w covers piece (s,w)
// = elems s*2048 + w*256 .. +255; lane l holds 8 elems via one 256-bit load.
__global__ __launch_bounds__(NTH) void k_partials(const float* __restrict__ f0,
                                                  const float* __restrict__ ps,
                                                  float* __restrict__ out,
                                                  int out_size) {
    const int b = blockIdx.y, cg = blockIdx.x;
    const double4* p4 = reinterpret_cast<const double4*>(f0 + (size_t)b * T
                         + (size_t)cg * CHUNK1);   // 2048 double4 per block
    const int t = threadIdx.x;
    const int lane = t & 31, wid = t >> 5;

    float s[CPB];
#pragma unroll
    for (int g = 0; g < 2; g++) {               // 2 batches of 4 compiler-scheduled loads
        double4 d[4];
#pragma unroll
        for (int k = 0; k < 4; k++)
            d[k] = p4[(g * 4 + k) * 256 + wid * 32 + lane];
#pragma unroll
        for (int k = 0; k < 4; k++)
            s[g * 4 + k] = sum8_of_d4(d[k]);
    }
#pragma unroll
    for (int dd = 16; dd; dd >>= 1) {
#pragma unroll
        for (int c = 0; c < CPB; c++) s[c] += __shfl_down_sync(FULL, s[c], dd);
    }
    __shared__ float ws[CPB][CPB];               // ws[slot][piece] = 256-sum
    if (lane == 0) {
#pragma unroll
        for (int c = 0; c < CPB; c++) ws[c][wid] = s[c];
    }
    __syncthreads();
    if (t < CPB) {                               // 2048-gran chunk sums
        float r = 0.f;
#pragma unroll
        for (int i = 0; i < CPB; i++) r += ws[t][i];
        g_partials[b * NCH + cg * CPB + t] = r * STEP;
    }
    if (t < CPB * CPB) {                         // 256-gran within-chunk excl prefix
        const int c = t >> 3, w = t & 7;
        float a = 0.f;
        for (int i = 0; i < w; i++) a += ws[c][i];
        g_subexcl[b * NSUB + cg * (CPB * CPB) + t] = a * STEP;
    }

    // ---- last block of this row performs the fp64 row scan (R5-verbatim) ----
    __shared__ int s_last;
    __syncthreads();
    if (t == 0) {
        __threadfence();
        s_last = (atomicAdd(&g_count[b], 1) == BPR - 1);
    }
    __syncthreads();
    if (!s_last) return;
    __threadfence();

    const float* pr = g_partials + b * NCH;
    const double v0 = (double)pr[2 * t];
    const double v1 = (double)pr[2 * t + 1];
    const double pair = v0 + v1;

    double incl = pair;
#pragma unroll
    for (int d = 1; d < 32; d <<= 1) {
        double n = __shfl_up_sync(FULL, incl, d);
        if (lane >= d) incl += n;
    }
    __shared__ double dwsum[NTH / 32];
    __shared__ double dwbase[NTH / 32];
    if (lane == 31) dwsum[wid] = incl;
    __syncthreads();
    if (t == 0) {
        double r = 0.0;
#pragma unroll
        for (int i = 0; i < NTH / 32; i++) { dwbase[i] = r; r += dwsum[i]; }
        g_count[b] = 0;                          // reset for next graph replay
    }
    __syncthreads();

    const double excl = (double)ps[b] + dwbase[wid] + (incl - pair);
    g_offsets[b * NCH + 2 * t]     = excl;
    g_offsets[b * NCH + 2 * t + 1] = excl + v0;

    if (t == NTH - 1) {                          // next_state (unwrapped)
        const long long oi = (long long)B * T + b;
        if (oi < (long long)out_size) out[oi] = (float)(excl + pair);
    }
}

// ------- Pass 2: barrier-free warp-per-256 + Rosenberg pulse (R14, 26.4us) ---
__global__ __launch_bounds__(NTH) void k_wav(const float* __restrict__ f0,
                                             const float* __restrict__ oq,
                                             float* __restrict__ out) {
    const int b = blockIdx.y, ch = blockIdx.x;   // ch = 2048-elem chunk
    const int lane = threadIdx.x & 31, wid = threadIdx.x >> 5;
    const int sub = ch * 8 + wid;                // warp's 256-elem piece
    const size_t base = (size_t)b * T + (size_t)sub * 256;

    const F8 f = ld8(f0 + base + lane * 8);      // default: may hit L2 from pass 1
    const F8 q = ld8_ef(oq + base + lane * 8);   // streaming

    float pr[8];
    float r = f.v[0] * STEP;          pr[0] = r;
#pragma unroll
    for (int i = 1; i < 8; i++) { r = fmaf(f.v[i], STEP, r); pr[i] = r; }
    const float tot = r;

    float incl = tot;
#pragma unroll
    for (int d = 1; d < 32; d <<= 1) {
        float n = __shfl_up_sync(FULL, incl, d);
        if (lane >= d) incl += n;
    }
    const float excl = incl - tot;

    // base: fp64 chunk offset + fp32 within-chunk 256-gran prefix (no barriers)
    const double based = g_offsets[b * NCH + ch];
    const float subx = g_subexcl[b * NSUB + sub];
    const float frac = (float)(based - floor(based));      // in [0, 1]
    const float baseph = frac + subx + excl;               // < 1.05 provable

    float w[8];
#pragma unroll
    for (int j = 0; j < 8; j++) {
        float ph = baseph + pr[j];
        ph -= (ph >= 1.f) ? 1.f : 0.f;           // cheap wrap
        const float oqv = q.v[j];
        const float tp = oqv * RISE_RATIO;
        const float tn = oqv - tp;
        const bool rise = ph < tp;
        const bool open = ph < oqv;
        const float num = rise ? ph : ph - tp;
        const float den = rise ? tp + EPSV : fmaf(2.f, tn, EPSV);
        const float c = __cosf(PI_F * __fdividef(num, den));
        const float res = rise ? fmaf(-0.5f, c, 0.5f) : c;
        w[j] = open ? res : 0.f;
    }

    st8_ef(out + base + lane * 8, w);            // streaming store
}

extern "C" void kernel_launch(void* const* d_in, const int* in_sizes, int n_in,
                              void* d_out, int out_size) {
    const float* f0 = (const float*)d_in[0];
    const float* oq = (const float*)d_in[1];
    const float* ps = (const float*)d_in[2];
    float* out = (float*)d_out;

    dim3 grid1(BPR, B);
    k_partials<<<grid1, NTH>>>(f0, ps, out, out_size);
    dim3 grid3(NCH, B);
    k_wav<<<grid3, NTH>>>(f0, oq, out);
}

// round 16
// speedup vs baseline: 1.0507x; 1.0507x over previous
#include <cuda_runtime.h>
#include <math.h>

#define B 16
#define T (1 << 20)
#define NTH 256
#define CHUNK 2048                // offset granule (fp64)
#define NCH (T / CHUNK)           // 512 chunks per row
#define NSUB (T / 256)            // 4096 256-elem pieces per row
#define CPB 8                     // chunks per pass-1 block
#define CHUNK1 (CHUNK * CPB)      // 16384 elems per pass-1 block
#define BPR (NCH / CPB)           // 64 pass-1 blocks per row
#define STEP (1.0f / 48000.0f)
#define RISE_RATIO 0.66f
#define EPSV 1e-6f
#define PI_F 3.14159265358979f
#define FULL 0xFFFFFFFFu

// scratch (no device-side allocation allowed)
__device__ float  g_partials[B * NCH];   // per-2048-elem sum of f0*STEP
__device__ double g_offsets[B * NCH];    // ps[b] + exclusive prefix across chunks
__device__ float  g_subexcl[B * NSUB];   // within-chunk exclusive prefix, 256-gran (x STEP)
__device__ int    g_count[B];            // per-row completion counters (self-resetting)

struct F8 { float v[8]; };

__device__ __forceinline__ F8 ld8(const float* p) {   // default cache policy (k_wav only)
    unsigned r0,r1,r2,r3,r4,r5,r6,r7;
    asm("ld.global.v8.b32 {%0,%1,%2,%3,%4,%5,%6,%7}, [%8];"
        : "=r"(r0),"=r"(r1),"=r"(r2),"=r"(r3),"=r"(r4),"=r"(r5),"=r"(r6),"=r"(r7)
        : "l"(p));
    F8 f;
    f.v[0]=__uint_as_float(r0); f.v[1]=__uint_as_float(r1);
    f.v[2]=__uint_as_float(r2); f.v[3]=__uint_as_float(r3);
    f.v[4]=__uint_as_float(r4); f.v[5]=__uint_as_float(r5);
    f.v[6]=__uint_as_float(r6); f.v[7]=__uint_as_float(r7);
    return f;
}
__device__ __forceinline__ F8 ld8_ef(const float* p) {  // L2 evict-first (streaming)
    unsigned r0,r1,r2,r3,r4,r5,r6,r7;
    asm("ld.global.L2::evict_first.v8.b32 {%0,%1,%2,%3,%4,%5,%6,%7}, [%8];"
        : "=r"(r0),"=r"(r1),"=r"(r2),"=r"(r3),"=r"(r4),"=r"(r5),"=r"(r6),"=r"(r7)
        : "l"(p));
    F8 f;
    f.v[0]=__uint_as_float(r0); f.v[1]=__uint_as_float(r1);
    f.v[2]=__uint_as_float(r2); f.v[3]=__uint_as_float(r3);
    f.v[4]=__uint_as_float(r4); f.v[5]=__uint_as_float(r5);
    f.v[6]=__uint_as_float(r6); f.v[7]=__uint_as_float(r7);
    return f;
}
__device__ __forceinline__ void st8_ef(float* p, const float* w) {
    asm volatile("st.global.L2::evict_first.v8.b32 [%0], {%1,%2,%3,%4,%5,%6,%7,%8};"
        :: "l"(p),
           "r"(__float_as_uint(w[0])), "r"(__float_as_uint(w[1])),
           "r"(__float_as_uint(w[2])), "r"(__float_as_uint(w[3])),
           "r"(__float_as_uint(w[4])), "r"(__float_as_uint(w[5])),
           "r"(__float_as_uint(w[6])), "r"(__float_as_uint(w[7])) : "memory");
}

// ------- Pass 1: R12 structure, remapped so warp w <-> contiguous 256-piece --
// Slot c: loadA = float4[c*512 + w*64 + l], loadB = float4[c*512 + w*64 + 32 + l].
// Each load: warp covers 512B contiguous (fully coalesced, 4 wf/LDG).
// Warp w's lane elems cover elems [c*2048 + w*256, +256) -> tree gives piece sum.
__global__ __launch_bounds__(NTH) void k_partials(const float* __restrict__ f0,
                                                  const float* __restrict__ ps,
                                                  float* __restrict__ out,
                                                  int out_size) {
    const int b = blockIdx.y, cg = blockIdx.x;
    const float4* p = reinterpret_cast<const float4*>(f0 + (size_t)b * T + (size_t)cg * CHUNK1);
    const int t = threadIdx.x;
    const int lane = t & 31, wid = t >> 5;
    const int wbase = wid * 64 + lane;

    float s[CPB];
    {
        float4 v[CPB];
#pragma unroll
        for (int c = 0; c < CPB; c++) v[c] = p[c * 512 + wbase];          // half A
#pragma unroll
        for (int c = 0; c < CPB; c++)
            s[c] = (v[c].x + v[c].y) + (v[c].z + v[c].w);
#pragma unroll
        for (int c = 0; c < CPB; c++) v[c] = p[c * 512 + wbase + 32];     // half B
#pragma unroll
        for (int c = 0; c < CPB; c++)
            s[c] += (v[c].x + v[c].y) + (v[c].z + v[c].w);
    }

#pragma unroll
    for (int d = 16; d; d >>= 1) {
#pragma unroll
        for (int c = 0; c < CPB; c++) s[c] += __shfl_down_sync(FULL, s[c], d);
    }
    __shared__ float ws[CPB][CPB];               // ws[chunk][piece] = 256-sum
    if (lane == 0) {
#pragma unroll
        for (int c = 0; c < CPB; c++) ws[c][wid] = s[c];
    }
    __syncthreads();
    if (t < CPB) {                               // 2048-gran chunk sums
        float r = 0.f;
#pragma unroll
        for (int i = 0; i < CPB; i++) r += ws[t][i];
        g_partials[b * NCH + cg * CPB + t] = r * STEP;
    }
    if (t < CPB * CPB) {                         // 256-gran within-chunk excl prefix
        const int c = t >> 3, w = t & 7;
        float a = 0.f;
        for (int i = 0; i < w; i++) a += ws[c][i];
        g_subexcl[b * NSUB + cg * (CPB * CPB) + t] = a * STEP;
    }

    // ---- last block of this row performs the fp64 row scan (R5-verbatim) ----
    __shared__ int s_last;
    __syncthreads();
    if (t == 0) {
        __threadfence();
        s_last = (atomicAdd(&g_count[b], 1) == BPR - 1);
    }
    __syncthreads();
    if (!s_last) return;
    __threadfence();

    const float* pr = g_partials + b * NCH;
    const double v0 = (double)pr[2 * t];
    const double v1 = (double)pr[2 * t + 1];
    const double pair = v0 + v1;

    double incl = pair;
#pragma unroll
    for (int d = 1; d < 32; d <<= 1) {
        double n = __shfl_up_sync(FULL, incl, d);
        if (lane >= d) incl += n;
    }
    __shared__ double dwsum[NTH / 32];
    __shared__ double dwbase[NTH / 32];
    if (lane == 31) dwsum[wid] = incl;
    __syncthreads();
    if (t == 0) {
        double r = 0.0;
#pragma unroll
        for (int i = 0; i < NTH / 32; i++) { dwbase[i] = r; r += dwsum[i]; }
        g_count[b] = 0;                          // reset for next graph replay
    }
    __syncthreads();

    const double excl = (double)ps[b] + dwbase[wid] + (incl - pair);
    g_offsets[b * NCH + 2 * t]     = excl;
    g_offsets[b * NCH + 2 * t + 1] = excl + v0;

    if (t == NTH - 1) {                          // next_state (unwrapped)
        const long long oi = (long long)B * T + b;
        if (oi < (long long)out_size) out[oi] = (float)(excl + pair);
    }
}

// ------- Pass 2: barrier-free warp-per-256 + Rosenberg pulse (R14, 26.4us) ---
__global__ __launch_bounds__(NTH) void k_wav(const float* __restrict__ f0,
                                             const float* __restrict__ oq,
                                             float* __restrict__ out) {
    const int b = blockIdx.y, ch = blockIdx.x;   // ch = 2048-elem chunk
    const int lane = threadIdx.x & 31, wid = threadIdx.x >> 5;
    const int sub = ch * 8 + wid;                // warp's 256-elem piece
    const size_t base = (size_t)b * T + (size_t)sub * 256;

    const F8 f = ld8(f0 + base + lane * 8);      // default: may hit L2 from pass 1
    const F8 q = ld8_ef(oq + base + lane * 8);   // streaming

    float pr[8];
    float r = f.v[0] * STEP;          pr[0] = r;
#pragma unroll
    for (int i = 1; i < 8; i++) { r = fmaf(f.v[i], STEP, r); pr[i] = r; }
    const float tot = r;

    float incl = tot;
#pragma unroll
    for (int d = 1; d < 32; d <<= 1) {
        float n = __shfl_up_sync(FULL, incl, d);
        if (lane >= d) incl += n;
    }
    const float excl = incl - tot;

    // base: fp64 chunk offset + fp32 within-chunk 256-gran prefix (no barriers)
    const double based = g_offsets[b * NCH + ch];
    const float subx = g_subexcl[b * NSUB + sub];
    const float frac = (float)(based - floor(based));      // in [0, 1]
    const float baseph = frac + subx + excl;               // < 1.05 provable

    float w[8];
#pragma unroll
    for (int j = 0; j < 8; j++) {
        float ph = baseph + pr[j];
        ph -= (ph >= 1.f) ? 1.f : 0.f;           // cheap wrap
        const float oqv = q.v[j];
        const float tp = oqv * RISE_RATIO;
        const float tn = oqv - tp;
        const bool rise = ph < tp;
        const bool open = ph < oqv;
        const float num = rise ? ph : ph - tp;
        const float den = rise ? tp + EPSV : fmaf(2.f, tn, EPSV);
        const float c = __cosf(PI_F * __fdividef(num, den));
        const float res = rise ? fmaf(-0.5f, c, 0.5f) : c;
        w[j] = open ? res : 0.f;
    }

    st8_ef(out + base + lane * 8, w);            // streaming store
}

extern "C" void kernel_launch(void* const* d_in, const int* in_sizes, int n_in,
                              void* d_out, int out_size) {
    const float* f0 = (const float*)d_in[0];
    const float* oq = (const float*)d_in[1];
    const float* ps = (const float*)d_in[2];
    float* out = (float*)d_out;

    dim3 grid1(BPR, B);
    k_partials<<<grid1, NTH>>>(f0, ps, out, out_size);
    dim3 grid3(NCH, B);
    k_wav<<<grid3, NTH>>>(f0, oq, out);
}